// round 1
// baseline (speedup 1.0000x reference)
#include <cuda_runtime.h>
#include <math.h>

#define B_  32
#define T_  2048
#define D_  512
#define H_  512
#define G4_ 2048   // 4*H

// ---------------- device scratch (allowed: __device__ globals) ----------------
__device__ float g_xp[(size_t)B_ * T_ * G4_];   // 512 MB x_proj scratch [B][T][4H]
__device__ float g_h[2][B_ * H_];               // double-buffered hidden state
__device__ unsigned int g_ctr;                  // grid barrier counter

// ---------------- packed f32x2 helpers ----------------
__device__ __forceinline__ unsigned long long pk(float lo, float hi) {
    unsigned long long r;
    asm("mov.b64 %0, {%1, %2};" : "=l"(r) : "f"(lo), "f"(hi));
    return r;
}
__device__ __forceinline__ unsigned long long fma2(unsigned long long a,
                                                   unsigned long long b,
                                                   unsigned long long c) {
    unsigned long long d;
    asm("fma.rn.f32x2 %0, %1, %2, %3;" : "=l"(d) : "l"(a), "l"(b), "l"(c));
    return d;
}

// ---------------- grid barrier primitives ----------------
__device__ __forceinline__ void red_add_release(unsigned int* p, unsigned int v) {
    asm volatile("red.release.gpu.add.u32 [%0], %1;" :: "l"(p), "r"(v) : "memory");
}
__device__ __forceinline__ unsigned int ld_acquire(unsigned int* p) {
    unsigned int v;
    asm volatile("ld.acquire.gpu.u32 %0, [%1];" : "=r"(v) : "l"(p) : "memory");
    return v;
}

// =====================================================================
// Phase 1: x_proj[M=65536, N=2048] = inputs[M,512] @ Wi[512,2048]
// BM=128, BN=128, BK=8, 256 threads, 8x8 micro-tile with f32x2 FMAs
// =====================================================================
#define BM 128
#define BN 128
#define BKK 8

__global__ __launch_bounds__(256) void gemm_xproj(const float* __restrict__ A,
                                                  const float* __restrict__ Bw) {
    __shared__ float As[BKK][BM + 4];
    __shared__ float Bs[BKK][BN + 4];

    const int tid = threadIdx.x;
    const int m0 = blockIdx.y * BM;
    const int n0 = blockIdx.x * BN;
    const int tx = tid & 15;        // 0..15 -> 8 cols each
    const int ty = tid >> 4;        // 0..15 -> 8 rows each

    const int arow = tid >> 1;           // 0..127
    const int akq  = (tid & 1) * 4;      // 0 or 4
    const int bkr  = tid >> 5;           // 0..7
    const int bq   = tid & 31;           // 0..31 (x4 floats)

    unsigned long long acc[8][4];
#pragma unroll
    for (int i = 0; i < 8; i++)
#pragma unroll
        for (int j = 0; j < 4; j++) acc[i][j] = 0ull;

    for (int kt = 0; kt < D_ / BKK; ++kt) {
        float4 av = *(const float4*)&A[(size_t)(m0 + arow) * D_ + kt * BKK + akq];
        As[akq + 0][arow] = av.x;
        As[akq + 1][arow] = av.y;
        As[akq + 2][arow] = av.z;
        As[akq + 3][arow] = av.w;
        float4 bv = *(const float4*)&Bw[(size_t)(kt * BKK + bkr) * G4_ + n0 + bq * 4];
        *(float4*)&Bs[bkr][bq * 4] = bv;
        __syncthreads();

#pragma unroll
        for (int k = 0; k < BKK; ++k) {
            float4 a0 = *(const float4*)&As[k][ty * 8];
            float4 a1 = *(const float4*)&As[k][ty * 8 + 4];
            const unsigned long long* bp = (const unsigned long long*)&Bs[k][tx * 8];
            unsigned long long b0 = bp[0], b1 = bp[1], b2 = bp[2], b3 = bp[3];
            float ar[8] = {a0.x, a0.y, a0.z, a0.w, a1.x, a1.y, a1.z, a1.w};
#pragma unroll
            for (int i = 0; i < 8; i++) {
                unsigned long long a2 = pk(ar[i], ar[i]);
                acc[i][0] = fma2(a2, b0, acc[i][0]);
                acc[i][1] = fma2(a2, b1, acc[i][1]);
                acc[i][2] = fma2(a2, b2, acc[i][2]);
                acc[i][3] = fma2(a2, b3, acc[i][3]);
            }
        }
        __syncthreads();
    }

#pragma unroll
    for (int i = 0; i < 8; i++) {
        size_t row = (size_t)(m0 + ty * 8 + i);
#pragma unroll
        for (int j = 0; j < 4; j++) {
            *(float2*)&g_xp[row * G4_ + n0 + tx * 8 + 2 * j] = *(float2*)&acc[i][j];
        }
    }
}

// =====================================================================
// Init: reset barrier counter, load h0 into h-buffer 0
// =====================================================================
__global__ void init_kernel(const float* __restrict__ h0) {
    int i = blockIdx.x * blockDim.x + threadIdx.x;
    if (i == 0) g_ctr = 0u;
    if (i < B_ * H_) g_h[0][i] = h0[i];
}

// =====================================================================
// Phase 2: persistent LSTM recurrence.
// 128 blocks x 256 threads. Block bl owns h-cols [bl*4, bl*4+4) ->
// 16 z-cols (4 gates). Wh slice lives in smem for the whole kernel.
// Grid barrier per timestep via release/acquire atomics.
// =====================================================================
__device__ __forceinline__ float sigf(float x) {
    return __fdividef(1.0f, 1.0f + __expf(-x));
}
__device__ __forceinline__ float tanhf_fast(float x) {
    return __fdividef(2.0f, 1.0f + __expf(-2.0f * x)) - 1.0f;
}

__global__ __launch_bounds__(256, 1) void lstm_seq(const float* __restrict__ c0,
                                                   const float* __restrict__ bias,
                                                   const float* __restrict__ Wh,
                                                   float* __restrict__ out) {
    __shared__ float w_s[16][516];   // [c][k], c = gate*4 + local h-col
    __shared__ float z_s[16][33];    // [c][b]
    __shared__ float c_s[4][32];     // [hc][b]
    __shared__ float b_s[16];

    const int tid = threadIdx.x;
    const int bl  = blockIdx.x;           // 0..127
    const unsigned int nblk = gridDim.x;  // 128

    // ---- load Wh slice + bias + c0 slice ----
    for (int idx = tid; idx < 16 * 512; idx += 256) {
        int c = idx >> 9;
        int k = idx & 511;
        int gcol = (c >> 2) * H_ + bl * 4 + (c & 3);
        w_s[c][k] = Wh[(size_t)k * G4_ + gcol];
    }
    if (tid < 16) b_s[tid] = bias[(tid >> 2) * H_ + bl * 4 + (tid & 3)];
    if (tid < 128) {
        int b = tid >> 2, hc = tid & 3;
        c_s[hc][b] = c0[b * H_ + bl * 4 + hc];
    }
    __syncthreads();

    // ---- per-thread dot assignment: 2 adjacent z-cols of one gate ----
    const int b   = tid >> 3;        // 0..31
    const int jj  = tid & 7;         // 0..7 -> col pair
    const int c0i = 2 * jj;          // local c index of first col
    const int g0  = c0i >> 2;
    const int j0  = c0i & 3;
    const int gcol0 = g0 * H_ + bl * 4 + j0;   // global z-col (and gcol0+1)
    const float bs0 = b_s[c0i];
    const float bs1 = b_s[c0i + 1];
    const float* xp_base = g_xp + (size_t)b * T_ * G4_ + gcol0;

    int par = 0;
    for (int t = 0; t < T_; ++t) {
        float2 xpv = *(const float2*)(xp_base + (size_t)t * G4_);
        const float* hsrc = g_h[par] + b * H_;

        // z-pair accumulators packed over k (even/odd lanes), hsum at the end
        unsigned long long acc0 = pk(xpv.x + bs0, 0.0f);
        unsigned long long acc1 = pk(xpv.y + bs1, 0.0f);

#pragma unroll 4
        for (int k = 0; k < H_; k += 4) {
            float4 hv = __ldcg((const float4*)(hsrc + k));   // bypass L1 (coherence)
            unsigned long long h01 = *(unsigned long long*)&hv.x;
            unsigned long long h23 = *(unsigned long long*)&hv.z;
            const unsigned long long* w0p = (const unsigned long long*)&w_s[c0i][k];
            const unsigned long long* w1p = (const unsigned long long*)&w_s[c0i + 1][k];
            acc0 = fma2(h01, w0p[0], acc0);
            acc0 = fma2(h23, w0p[1], acc0);
            acc1 = fma2(h01, w1p[0], acc1);
            acc1 = fma2(h23, w1p[1], acc1);
        }
        float2 r0 = *(float2*)&acc0;
        float2 r1 = *(float2*)&acc1;
        z_s[c0i][b]     = r0.x + r0.y;
        z_s[c0i + 1][b] = r1.x + r1.y;
        __syncthreads();

        // ---- gates: 128 threads = 32 batches x 4 h-cols ----
        if (tid < 128) {
            int bb = tid >> 2, hc = tid & 3;
            float zi = z_s[hc][bb];
            float zf = z_s[4 + hc][bb];
            float zg = z_s[8 + hc][bb];
            float zo = z_s[12 + hc][bb];
            float cn = sigf(zf) * c_s[hc][bb] + sigf(zi) * tanhf_fast(zg);
            float hn = sigf(zo) * tanhf_fast(cn);
            c_s[hc][bb] = cn;
            int hcol = bl * 4 + hc;
            g_h[par ^ 1][bb * H_ + hcol] = hn;
            out[((size_t)bb * T_ + t) * H_ + hcol] = hn;
        }
        __syncthreads();

        // ---- grid barrier (release arrive / acquire poll) ----
        if (tid == 0) {
            red_add_release(&g_ctr, 1u);
            unsigned int tgt = (unsigned int)(t + 1) * nblk;
            while (ld_acquire(&g_ctr) < tgt) { }
        }
        __syncthreads();
        par ^= 1;
    }
}

// =====================================================================
// launch
// =====================================================================
extern "C" void kernel_launch(void* const* d_in, const int* in_sizes, int n_in,
                              void* d_out, int out_size) {
    const float* inputs = (const float*)d_in[0];
    // d_in[1] = input_paddings (unused: all tokens valid in reference path)
    const float* c0   = (const float*)d_in[2];
    const float* h0   = (const float*)d_in[3];
    const float* Wi   = (const float*)d_in[4];
    const float* Wh   = (const float*)d_in[5];
    const float* bias = (const float*)d_in[6];
    float* out = (float*)d_out;

    dim3 g1(G4_ / BN, (B_ * T_) / BM);   // 16 x 512
    gemm_xproj<<<g1, 256>>>(inputs, Wi);
    init_kernel<<<64, 256>>>(h0);
    lstm_seq<<<128, 256>>>(c0, bias, Wh, out);
}

// round 3
// speedup vs baseline: 1.8191x; 1.8191x over previous
#include <cuda_runtime.h>
#include <math.h>

#define B_  32
#define T_  2048
#define D_  512
#define H_  512
#define G4_ 2048   // 4*H

// ---------------- device scratch ----------------
__device__ float g_xp[(size_t)B_ * T_ * G4_];   // x_proj scratch [B][T][4H]
__device__ float g_h[2][B_ * H_];               // double-buffered hidden state
__device__ unsigned int g_ctr;                  // grid barrier counter

typedef unsigned long long ull;

// ---------------- packed f32x2 helpers ----------------
__device__ __forceinline__ ull pk(float lo, float hi) {
    ull r;
    asm("mov.b64 %0, {%1, %2};" : "=l"(r) : "f"(lo), "f"(hi));
    return r;
}
__device__ __forceinline__ ull fma2(ull a, ull b, ull c) {
    ull d;
    asm("fma.rn.f32x2 %0, %1, %2, %3;" : "=l"(d) : "l"(a), "l"(b), "l"(c));
    return d;
}

// ---------------- grid barrier primitives ----------------
__device__ __forceinline__ void red_add_release(unsigned int* p, unsigned int v) {
    asm volatile("red.release.gpu.add.u32 [%0], %1;" :: "l"(p), "r"(v) : "memory");
}
__device__ __forceinline__ unsigned int ld_acquire(unsigned int* p) {
    unsigned int v;
    asm volatile("ld.acquire.gpu.u32 %0, [%1];" : "=r"(v) : "l"(p) : "memory");
    return v;
}

// =====================================================================
// Phase 1: x_proj[65536, 2048] = inputs[65536,512] @ Wi[512,2048]
// (unchanged — ~3 ms, fma-bound; optimize in a later round)
// =====================================================================
#define BM 128
#define BN 128
#define BKK 8

__global__ __launch_bounds__(256) void gemm_xproj(const float* __restrict__ A,
                                                  const float* __restrict__ Bw) {
    __shared__ float As[BKK][BM + 4];
    __shared__ float Bs[BKK][BN + 4];

    const int tid = threadIdx.x;
    const int m0 = blockIdx.y * BM;
    const int n0 = blockIdx.x * BN;
    const int tx = tid & 15;
    const int ty = tid >> 4;

    const int arow = tid >> 1;
    const int akq  = (tid & 1) * 4;
    const int bkr  = tid >> 5;
    const int bq   = tid & 31;

    ull acc[8][4];
#pragma unroll
    for (int i = 0; i < 8; i++)
#pragma unroll
        for (int j = 0; j < 4; j++) acc[i][j] = 0ull;

    for (int kt = 0; kt < D_ / BKK; ++kt) {
        float4 av = *(const float4*)&A[(size_t)(m0 + arow) * D_ + kt * BKK + akq];
        As[akq + 0][arow] = av.x;
        As[akq + 1][arow] = av.y;
        As[akq + 2][arow] = av.z;
        As[akq + 3][arow] = av.w;
        float4 bv = *(const float4*)&Bw[(size_t)(kt * BKK + bkr) * G4_ + n0 + bq * 4];
        *(float4*)&Bs[bkr][bq * 4] = bv;
        __syncthreads();

#pragma unroll
        for (int k = 0; k < BKK; ++k) {
            float4 a0 = *(const float4*)&As[k][ty * 8];
            float4 a1 = *(const float4*)&As[k][ty * 8 + 4];
            const ull* bp = (const ull*)&Bs[k][tx * 8];
            ull b0 = bp[0], b1 = bp[1], b2 = bp[2], b3 = bp[3];
            float ar[8] = {a0.x, a0.y, a0.z, a0.w, a1.x, a1.y, a1.z, a1.w};
#pragma unroll
            for (int i = 0; i < 8; i++) {
                ull a2 = pk(ar[i], ar[i]);
                acc[i][0] = fma2(a2, b0, acc[i][0]);
                acc[i][1] = fma2(a2, b1, acc[i][1]);
                acc[i][2] = fma2(a2, b2, acc[i][2]);
                acc[i][3] = fma2(a2, b3, acc[i][3]);
            }
        }
        __syncthreads();
    }

#pragma unroll
    for (int i = 0; i < 8; i++) {
        size_t row = (size_t)(m0 + ty * 8 + i);
#pragma unroll
        for (int j = 0; j < 4; j++) {
            *(float2*)&g_xp[row * G4_ + n0 + tx * 8 + 2 * j] = *(float2*)&acc[i][j];
        }
    }
}

// =====================================================================
// Init: reset barrier counter, load h0
// =====================================================================
__global__ void init_kernel(const float* __restrict__ h0) {
    int i = blockIdx.x * blockDim.x + threadIdx.x;
    if (i == 0) g_ctr = 0u;
    if (i < B_ * H_) g_h[0][i] = h0[i];
}

// =====================================================================
// Phase 2: persistent LSTM recurrence (v3)
// 128 blocks x 256 threads. Block owns 16 z-cols (4 h-cols).
// Thread (kq, bg, cp): 4 batches x 2 cols x 128 k's.
// Weight smem: rows of 512 floats (16B-aligned), ROTATED by 4*(c>>1)
// floats per column-pair -> LDS.128 conflict-free AND aligned.
// =====================================================================
__device__ __forceinline__ float sigf(float x) {
    return __fdividef(1.0f, 1.0f + __expf(-x));
}
__device__ __forceinline__ float tanhf_fast(float x) {
    return __fdividef(2.0f, 1.0f + __expf(-2.0f * x)) - 1.0f;
}

__global__ __launch_bounds__(256, 1) void lstm_seq(const float* __restrict__ c0,
                                                   const float* __restrict__ bias,
                                                   const float* __restrict__ Wh,
                                                   float* __restrict__ out) {
    __shared__ __align__(16) float w_s[16][512];   // 32 KB, rotated rows
    __shared__ __align__(16) float part[4][32][16]; // 8 KB [kq][b][c]
    __shared__ float z_s[16][33];
    __shared__ float c_s[4][32];
    __shared__ float b_s[16];

    const int tid = threadIdx.x;
    const int bl  = blockIdx.x;           // 0..127
    const unsigned int nblk = gridDim.x;

    // ---- compute-phase mapping: tid = kq*64 + bg*8 + cp ----
    const int cp  = tid & 7;              // col pair 0..7
    const int bg  = (tid >> 3) & 7;       // batch group (4 batches)
    const int kq  = tid >> 6;             // k quarter 0..3
    const int k0  = kq * 128;
    const int b0i = bg * 4;
    const int rot = 4 * cp;               // row-pair rotation (floats)

    // ---- assembly/gate mapping: tid = b*8 + cp ----
    const int ab  = tid >> 3;             // 0..31
    const int ac0 = 2 * (tid & 7);        // local col of pair
    const int agc = (ac0 >> 2) * H_ + bl * 4 + (ac0 & 3);  // global z-col

    // ---- load Wh slice (rotated), bias, c0 ----
    for (int idx = tid; idx < 16 * 512; idx += 256) {
        int c = idx & 15;
        int k = idx >> 4;
        int gcol = (c >> 2) * H_ + bl * 4 + (c & 3);
        w_s[c][(k + 4 * (c >> 1)) & 511] = Wh[(size_t)k * G4_ + gcol];
    }
    if (tid < 16) b_s[tid] = bias[(tid >> 2) * H_ + bl * 4 + (tid & 3)];
    if (tid < 128) {
        int b = tid >> 2, hc = tid & 3;
        c_s[hc][b] = c0[b * H_ + bl * 4 + hc];
    }
    __syncthreads();

    const float* w0row = w_s[2 * cp];
    const float* w1row = w_s[2 * cp + 1];
    const float  bs0 = b_s[ac0];
    const float  bs1 = b_s[ac0 + 1];
    const float* xp_base = g_xp + (size_t)ab * T_ * G4_ + agc;

    int par = 0;
    for (int t = 0; t < T_; ++t) {
        float2 xpv = __ldcs((const float2*)(xp_base + (size_t)t * G4_));

        const float* hsrc = g_h[par];

        ull acc[4][2];
#pragma unroll
        for (int bi = 0; bi < 4; ++bi) { acc[bi][0] = 0ull; acc[bi][1] = 0ull; }

#pragma unroll 4
        for (int kk = 0; kk < 128; kk += 4) {
            const int k   = k0 + kk;
            const int idx = (k + rot) & 511;              // aligned, conflict-free
            float4 w0 = *(const float4*)&w0row[idx];
            float4 w1 = *(const float4*)&w1row[idx];
            ull w0a = ((const ull*)&w0)[0], w0b = ((const ull*)&w0)[1];
            ull w1a = ((const ull*)&w1)[0], w1b = ((const ull*)&w1)[1];
#pragma unroll
            for (int bi = 0; bi < 4; ++bi) {
                float4 hv = __ldcg((const float4*)(hsrc + (b0i + bi) * H_ + k));
                ull h01 = ((const ull*)&hv)[0], h23 = ((const ull*)&hv)[1];
                acc[bi][0] = fma2(h01, w0a, acc[bi][0]);
                acc[bi][0] = fma2(h23, w0b, acc[bi][0]);
                acc[bi][1] = fma2(h01, w1a, acc[bi][1]);
                acc[bi][1] = fma2(h23, w1b, acc[bi][1]);
            }
        }

        // horizontal add over k-parity, stash partials
#pragma unroll
        for (int bi = 0; bi < 4; ++bi) {
            float2 p0 = *(float2*)&acc[bi][0];
            float2 p1 = *(float2*)&acc[bi][1];
            float2 pr;
            pr.x = p0.x + p0.y;
            pr.y = p1.x + p1.y;
            *(float2*)&part[kq][b0i + bi][2 * cp] = pr;
        }
        __syncthreads();

        // ---- assemble z: 256 threads = 32 b x 8 col-pairs ----
        {
            float2 q0 = *(const float2*)&part[0][ab][ac0];
            float2 q1 = *(const float2*)&part[1][ab][ac0];
            float2 q2 = *(const float2*)&part[2][ab][ac0];
            float2 q3 = *(const float2*)&part[3][ab][ac0];
            z_s[ac0][ab]     = xpv.x + bs0 + ((q0.x + q1.x) + (q2.x + q3.x));
            z_s[ac0 + 1][ab] = xpv.y + bs1 + ((q0.y + q1.y) + (q2.y + q3.y));
        }
        __syncthreads();

        // ---- gates: 128 threads = 32 b x 4 h-cols ----
        if (tid < 128) {
            int bb = tid >> 2, hc = tid & 3;
            float zi = z_s[hc][bb];
            float zf = z_s[4 + hc][bb];
            float zg = z_s[8 + hc][bb];
            float zo = z_s[12 + hc][bb];
            float cn = sigf(zf) * c_s[hc][bb] + sigf(zi) * tanhf_fast(zg);
            float hn = sigf(zo) * tanhf_fast(cn);
            c_s[hc][bb] = cn;
            int hcol = bl * 4 + hc;
            g_h[par ^ 1][bb * H_ + hcol] = hn;
            __stcs(&out[((size_t)bb * T_ + t) * H_ + hcol], hn);
        }
        __syncthreads();

        // ---- grid barrier ----
        if (tid == 0) {
            red_add_release(&g_ctr, 1u);
            unsigned int tgt = (unsigned int)(t + 1) * nblk;
            while (ld_acquire(&g_ctr) < tgt) { }
        }
        __syncthreads();
        par ^= 1;
    }
}

// =====================================================================
// launch
// =====================================================================
extern "C" void kernel_launch(void* const* d_in, const int* in_sizes, int n_in,
                              void* d_out, int out_size) {
    const float* inputs = (const float*)d_in[0];
    // d_in[1] = input_paddings (unused: all tokens valid)
    const float* c0   = (const float*)d_in[2];
    const float* h0   = (const float*)d_in[3];
    const float* Wi   = (const float*)d_in[4];
    const float* Wh   = (const float*)d_in[5];
    const float* bias = (const float*)d_in[6];
    float* out = (float*)d_out;

    dim3 g1(G4_ / BN, (B_ * T_) / BM);   // 16 x 512
    gemm_xproj<<<g1, 256>>>(inputs, Wi);
    init_kernel<<<64, 256>>>(h0);
    lstm_seq<<<128, 256>>>(c0, bias, Wh, out);
}

// round 4
// speedup vs baseline: 2.2839x; 1.2555x over previous
#include <cuda_runtime.h>
#include <math.h>

#define B_  32
#define T_  2048
#define D_  512
#define H_  512
#define G4_ 2048   // 4*H

// ---------------- device scratch ----------------
__device__ float g_xp[(size_t)B_ * T_ * G4_];   // x_proj scratch [B][T][4H]
__device__ float g_h[2][B_ * H_];               // double-buffered hidden state
__device__ unsigned int g_ctr;                  // grid barrier counter

typedef unsigned long long ull;

// ---------------- packed f32x2 helpers ----------------
__device__ __forceinline__ ull pk(float lo, float hi) {
    ull r;
    asm("mov.b64 %0, {%1, %2};" : "=l"(r) : "f"(lo), "f"(hi));
    return r;
}
__device__ __forceinline__ ull fma2(ull a, ull b, ull c) {
    ull d;
    asm("fma.rn.f32x2 %0, %1, %2, %3;" : "=l"(d) : "l"(a), "l"(b), "l"(c));
    return d;
}

// ---------------- grid barrier primitives ----------------
__device__ __forceinline__ void red_add_release(unsigned int* p, unsigned int v) {
    asm volatile("red.release.gpu.add.u32 [%0], %1;" :: "l"(p), "r"(v) : "memory");
}
__device__ __forceinline__ unsigned int ld_acquire(unsigned int* p) {
    unsigned int v;
    asm volatile("ld.acquire.gpu.u32 %0, [%1];" : "=r"(v) : "l"(p) : "memory");
    return v;
}

// =====================================================================
// Phase 1: x_proj[65536, 2048] = inputs[65536,512] @ Wi[512,2048]
// (~3 ms, fma-bound; next optimization target)
// =====================================================================
#define BM 128
#define BN 128
#define BKK 8

__global__ __launch_bounds__(256) void gemm_xproj(const float* __restrict__ A,
                                                  const float* __restrict__ Bw) {
    __shared__ float As[BKK][BM + 4];
    __shared__ float Bs[BKK][BN + 4];

    const int tid = threadIdx.x;
    const int m0 = blockIdx.y * BM;
    const int n0 = blockIdx.x * BN;
    const int tx = tid & 15;
    const int ty = tid >> 4;

    const int arow = tid >> 1;
    const int akq  = (tid & 1) * 4;
    const int bkr  = tid >> 5;
    const int bq   = tid & 31;

    ull acc[8][4];
#pragma unroll
    for (int i = 0; i < 8; i++)
#pragma unroll
        for (int j = 0; j < 4; j++) acc[i][j] = 0ull;

    for (int kt = 0; kt < D_ / BKK; ++kt) {
        float4 av = *(const float4*)&A[(size_t)(m0 + arow) * D_ + kt * BKK + akq];
        As[akq + 0][arow] = av.x;
        As[akq + 1][arow] = av.y;
        As[akq + 2][arow] = av.z;
        As[akq + 3][arow] = av.w;
        float4 bv = *(const float4*)&Bw[(size_t)(kt * BKK + bkr) * G4_ + n0 + bq * 4];
        *(float4*)&Bs[bkr][bq * 4] = bv;
        __syncthreads();

#pragma unroll
        for (int k = 0; k < BKK; ++k) {
            float4 a0 = *(const float4*)&As[k][ty * 8];
            float4 a1 = *(const float4*)&As[k][ty * 8 + 4];
            const ull* bp = (const ull*)&Bs[k][tx * 8];
            ull b0 = bp[0], b1 = bp[1], b2 = bp[2], b3 = bp[3];
            float ar[8] = {a0.x, a0.y, a0.z, a0.w, a1.x, a1.y, a1.z, a1.w};
#pragma unroll
            for (int i = 0; i < 8; i++) {
                ull a2 = pk(ar[i], ar[i]);
                acc[i][0] = fma2(a2, b0, acc[i][0]);
                acc[i][1] = fma2(a2, b1, acc[i][1]);
                acc[i][2] = fma2(a2, b2, acc[i][2]);
                acc[i][3] = fma2(a2, b3, acc[i][3]);
            }
        }
        __syncthreads();
    }

#pragma unroll
    for (int i = 0; i < 8; i++) {
        size_t row = (size_t)(m0 + ty * 8 + i);
#pragma unroll
        for (int j = 0; j < 4; j++) {
            *(float2*)&g_xp[row * G4_ + n0 + tx * 8 + 2 * j] = *(float2*)&acc[i][j];
        }
    }
}

// =====================================================================
// Init: reset barrier counter, load h0
// =====================================================================
__global__ void init_kernel(const float* __restrict__ h0) {
    int i = blockIdx.x * blockDim.x + threadIdx.x;
    if (i == 0) g_ctr = 0u;
    if (i < B_ * H_) g_h[0][i] = h0[i];
}

// =====================================================================
// Phase 2: persistent LSTM recurrence (v4)
// h staged into smem each step -> kills the 8x redundant L2 traffic.
// Dynamic smem (~108 KB): w_s[16][512] | h_s[32][516] | part | z | c | b
// =====================================================================
#define HSTRIDE 516   // h_s row stride: 516*4B = 2064B, 16B-aligned,
                      // 4 bg-rows land on distinct bank groups

__device__ __forceinline__ float sigf(float x) {
    return __fdividef(1.0f, 1.0f + __expf(-x));
}
__device__ __forceinline__ float tanhf_fast(float x) {
    return __fdividef(2.0f, 1.0f + __expf(-2.0f * x)) - 1.0f;
}

extern __shared__ float smem_dyn[];

__global__ __launch_bounds__(256, 1) void lstm_seq(const float* __restrict__ c0,
                                                   const float* __restrict__ bias,
                                                   const float* __restrict__ Wh,
                                                   float* __restrict__ out) {
    // ---- carve dynamic smem ----
    float (*w_s)[512] = (float (*)[512])smem_dyn;                 // 32 KB
    float* h_s = smem_dyn + 16 * 512;                             // 32*516 = 66048 B... (floats)
    float (*part)[32][16] = (float (*)[32][16])(h_s + 32 * HSTRIDE); // 8 KB
    float (*z_s)[33] = (float (*)[33])((float*)part + 4 * 32 * 16);
    float (*c_s)[32] = (float (*)[32])((float*)z_s + 16 * 33);
    float* b_s = (float*)c_s + 4 * 32;

    const int tid = threadIdx.x;
    const int bl  = blockIdx.x;           // 0..127
    const unsigned int nblk = gridDim.x;

    // ---- compute-phase mapping: tid = kq*64 + bg*8 + cp ----
    const int cp  = tid & 7;              // col pair 0..7
    const int bg  = (tid >> 3) & 7;       // batch group (4 batches)
    const int kq  = tid >> 6;             // k quarter 0..3
    const int k0  = kq * 128;
    const int b0i = bg * 4;
    const int rot = 4 * cp;               // row-pair rotation (floats)

    // ---- assembly/gate mapping ----
    const int ab  = tid >> 3;             // 0..31
    const int ac0 = 2 * (tid & 7);        // local col of pair
    const int agc = (ac0 >> 2) * H_ + bl * 4 + (ac0 & 3);  // global z-col

    // ---- load Wh slice (rotated), bias, c0 ----
    for (int idx = tid; idx < 16 * 512; idx += 256) {
        int c = idx & 15;
        int k = idx >> 4;
        int gcol = (c >> 2) * H_ + bl * 4 + (c & 3);
        w_s[c][(k + 4 * (c >> 1)) & 511] = Wh[(size_t)k * G4_ + gcol];
    }
    if (tid < 16) b_s[tid] = bias[(tid >> 2) * H_ + bl * 4 + (tid & 3)];
    if (tid < 128) {
        int b = tid >> 2, hc = tid & 3;
        c_s[hc][b] = c0[b * H_ + bl * 4 + hc];
    }
    __syncthreads();

    const float* w0row = w_s[2 * cp];
    const float* w1row = w_s[2 * cp + 1];
    const float  bs0 = b_s[ac0];
    const float  bs1 = b_s[ac0 + 1];
    const float* xp_base = g_xp + (size_t)ab * T_ * G4_ + agc;

    int par = 0;
    for (int t = 0; t < T_; ++t) {
        // ---- stage h into smem (16 float4 per thread, coalesced) ----
        const float* hsrc = g_h[par];
        float4 hreg[16];
#pragma unroll
        for (int i = 0; i < 16; ++i) {
            int idx4 = tid + i * 256;                 // 0..4095
            hreg[i] = __ldcg((const float4*)(hsrc + idx4 * 4));
        }
        float2 xpv = __ldcs((const float2*)(xp_base + (size_t)t * G4_));
#pragma unroll
        for (int i = 0; i < 16; ++i) {
            int idx4 = tid + i * 256;
            int b  = idx4 >> 7;                       // 128 float4 per batch row
            int k4 = idx4 & 127;
            *(float4*)&h_s[b * HSTRIDE + k4 * 4] = hreg[i];
        }
        __syncthreads();

        ull acc[4][2];
#pragma unroll
        for (int bi = 0; bi < 4; ++bi) { acc[bi][0] = 0ull; acc[bi][1] = 0ull; }

#pragma unroll 4
        for (int kk = 0; kk < 128; kk += 4) {
            const int k   = k0 + kk;
            const int idx = (k + rot) & 511;          // aligned, conflict-free
            float4 w0 = *(const float4*)&w0row[idx];
            float4 w1 = *(const float4*)&w1row[idx];
            ull w0a = ((const ull*)&w0)[0], w0b = ((const ull*)&w0)[1];
            ull w1a = ((const ull*)&w1)[0], w1b = ((const ull*)&w1)[1];
#pragma unroll
            for (int bi = 0; bi < 4; ++bi) {
                float4 hv = *(const float4*)&h_s[(b0i + bi) * HSTRIDE + k];  // 8x broadcast
                ull h01 = ((const ull*)&hv)[0], h23 = ((const ull*)&hv)[1];
                acc[bi][0] = fma2(h01, w0a, acc[bi][0]);
                acc[bi][0] = fma2(h23, w0b, acc[bi][0]);
                acc[bi][1] = fma2(h01, w1a, acc[bi][1]);
                acc[bi][1] = fma2(h23, w1b, acc[bi][1]);
            }
        }

        // horizontal add over k-parity, stash partials
#pragma unroll
        for (int bi = 0; bi < 4; ++bi) {
            float2 p0 = *(float2*)&acc[bi][0];
            float2 p1 = *(float2*)&acc[bi][1];
            float2 pr;
            pr.x = p0.x + p0.y;
            pr.y = p1.x + p1.y;
            *(float2*)&part[kq][b0i + bi][2 * cp] = pr;
        }
        __syncthreads();

        // ---- assemble z: 256 threads = 32 b x 8 col-pairs ----
        {
            float2 q0 = *(const float2*)&part[0][ab][ac0];
            float2 q1 = *(const float2*)&part[1][ab][ac0];
            float2 q2 = *(const float2*)&part[2][ab][ac0];
            float2 q3 = *(const float2*)&part[3][ab][ac0];
            z_s[ac0][ab]     = xpv.x + bs0 + ((q0.x + q1.x) + (q2.x + q3.x));
            z_s[ac0 + 1][ab] = xpv.y + bs1 + ((q0.y + q1.y) + (q2.y + q3.y));
        }
        __syncthreads();

        // ---- gates: 128 threads = 32 b x 4 h-cols ----
        if (tid < 128) {
            int bb = tid >> 2, hc = tid & 3;
            float zi = z_s[hc][bb];
            float zf = z_s[4 + hc][bb];
            float zg = z_s[8 + hc][bb];
            float zo = z_s[12 + hc][bb];
            float cn = sigf(zf) * c_s[hc][bb] + sigf(zi) * tanhf_fast(zg);
            float hn = sigf(zo) * tanhf_fast(cn);
            c_s[hc][bb] = cn;
            int hcol = bl * 4 + hc;
            g_h[par ^ 1][bb * H_ + hcol] = hn;
            __stcs(&out[((size_t)bb * T_ + t) * H_ + hcol], hn);
        }
        __syncthreads();

        // ---- grid barrier ----
        if (tid == 0) {
            red_add_release(&g_ctr, 1u);
            unsigned int tgt = (unsigned int)(t + 1) * nblk;
            while (ld_acquire(&g_ctr) < tgt) { }
        }
        __syncthreads();
        par ^= 1;
    }
}

// =====================================================================
// launch
// =====================================================================
#define LSTM_SMEM_BYTES ((16 * 512 + 32 * HSTRIDE + 4 * 32 * 16 + 16 * 33 + 4 * 32 + 16) * 4)

extern "C" void kernel_launch(void* const* d_in, const int* in_sizes, int n_in,
                              void* d_out, int out_size) {
    const float* inputs = (const float*)d_in[0];
    // d_in[1] = input_paddings (unused: all tokens valid)
    const float* c0   = (const float*)d_in[2];
    const float* h0   = (const float*)d_in[3];
    const float* Wi   = (const float*)d_in[4];
    const float* Wh   = (const float*)d_in[5];
    const float* bias = (const float*)d_in[6];
    float* out = (float*)d_out;

    cudaFuncSetAttribute(lstm_seq, cudaFuncAttributeMaxDynamicSharedMemorySize,
                         LSTM_SMEM_BYTES);

    dim3 g1(G4_ / BN, (B_ * T_) / BM);   // 16 x 512
    gemm_xproj<<<g1, 256>>>(inputs, Wi);
    init_kernel<<<64, 256>>>(h0);
    lstm_seq<<<128, 256, LSTM_SMEM_BYTES>>>(c0, bias, Wh, out);
}